// round 2
// baseline (speedup 1.0000x reference)
#include <cuda_runtime.h>
#include <cuda_bf16.h>

// DimMasking: out = mask * x where mask is produced by a 64-iteration
// sharpened-softmax dropout recurrence on h = MLP(x).
//
// Layout: one warp per row (D=640 => 20 elems/lane in registers),
// 8 warps (8 rows) per CTA. MLP done as per-warp GEMVs with the row
// staged in smem; W1/W2 stay hot in L1 across the CTA's 8 warps.

#define DD       640
#define HID      64
#define N_ITER   64
#define EPSF     1e-7f
#define INV_T    (1.0f / 0.07f)
#define RPC      8            // rows per CTA
#define KPL      20           // elements per lane = 640/32

__global__ __launch_bounds__(RPC * 32)
void dim_masking_kernel(const float* __restrict__ x,
                        const float* __restrict__ W1,
                        const float* __restrict__ b1,
                        const float* __restrict__ W2,
                        const float* __restrict__ b2,
                        float* __restrict__ out)
{
    __shared__ float xs[RPC][DD];
    __shared__ float hs[RPC][HID];

    const int w    = threadIdx.x >> 5;
    const int lane = threadIdx.x & 31;
    const int row  = blockIdx.x * RPC + w;

    const float* xr = x + (size_t)row * DD;

    // ---- stage x row into smem (coalesced) ----
    #pragma unroll
    for (int k = 0; k < KPL; k++)
        xs[w][lane + 32 * k] = xr[lane + 32 * k];
    __syncwarp();

    // ---- GEMM1: h_hid = relu(x @ W1 + b1); lane computes units 2l, 2l+1 ----
    float2 acc1 = *(const float2*)&b1[2 * lane];
    #pragma unroll 8
    for (int d = 0; d < DD; d++) {
        float  xd = xs[w][d];
        float2 wv = *(const float2*)&W1[d * HID + 2 * lane];
        acc1.x = fmaf(xd, wv.x, acc1.x);
        acc1.y = fmaf(xd, wv.y, acc1.y);
    }
    hs[w][2 * lane]     = fmaxf(acc1.x, 0.0f);
    hs[w][2 * lane + 1] = fmaxf(acc1.y, 0.0f);
    __syncwarp();

    // ---- GEMM2: h = h_hid @ W2 + b2; lane owns j = lane + 32k ----
    float nh[KPL];   // will hold -h
    #pragma unroll
    for (int k = 0; k < KPL; k++)
        nh[k] = b2[lane + 32 * k];
    #pragma unroll 4
    for (int c = 0; c < HID; c++) {
        float hc = hs[w][c];
        const float* w2r = &W2[c * DD + lane];
        #pragma unroll
        for (int k = 0; k < KPL; k++)
            nh[k] = fmaf(hc, w2r[32 * k], nh[k]);
    }
    #pragma unroll
    for (int k = 0; k < KPL; k++)
        nh[k] = -nh[k];

    // ---- iterative masking recurrence (register-resident) ----
    float hhat[KPL];
    #pragma unroll
    for (int k = 0; k < KPL; k++) hhat[k] = 0.0f;

    float t[KPL];
    for (int it = 0; it < N_ITER; it++) {
        // logits = (-h + log(m + eps)) / TEMP, with m = 1 - hhat
        float M = -3.402823e38f;
        #pragma unroll
        for (int k = 0; k < KPL; k++) {
            float m  = 1.0f - hhat[k];
            float lk = (nh[k] + __logf(m + EPSF)) * INV_T;
            t[k] = lk;
            M = fmaxf(M, lk);
        }
        #pragma unroll
        for (int o = 16; o > 0; o >>= 1)
            M = fmaxf(M, __shfl_xor_sync(0xffffffffu, M, o));

        // softmax numerator + sum
        float S = 0.0f;
        #pragma unroll
        for (int k = 0; k < KPL; k++) {
            float e = __expf(t[k] - M);
            t[k] = e;
            S += e;
        }
        #pragma unroll
        for (int o = 16; o > 0; o >>= 1)
            S += __shfl_xor_sync(0xffffffffu, S, o);
        float rS = __fdividef(1.0f, S);

        // hhat += yhat * m   (reference ordering)
        #pragma unroll
        for (int k = 0; k < KPL; k++) {
            float m = 1.0f - hhat[k];
            hhat[k] = fmaf(t[k] * rS, m, hhat[k]);
        }
    }

    // ---- out = (1 - hhat) * x ----
    float* orow = out + (size_t)row * DD;
    #pragma unroll
    for (int k = 0; k < KPL; k++)
        orow[lane + 32 * k] = (1.0f - hhat[k]) * xs[w][lane + 32 * k];
}

extern "C" void kernel_launch(void* const* d_in, const int* in_sizes, int n_in,
                              void* d_out, int out_size)
{
    const float* x  = (const float*)d_in[0];   // (8192, 640)
    const float* W1 = (const float*)d_in[1];   // (640, 64)
    const float* b1 = (const float*)d_in[2];   // (64,)
    const float* W2 = (const float*)d_in[3];   // (64, 640)
    const float* b2 = (const float*)d_in[4];   // (640,)
    float* out = (float*)d_out;

    const int B = in_sizes[0] / DD;            // 8192
    dim_masking_kernel<<<B / RPC, RPC * 32>>>(x, W1, b1, W2, b2, out);
}

// round 3
// speedup vs baseline: 1.4071x; 1.4071x over previous
#include <cuda_runtime.h>
#include <cuda_bf16.h>

// DimMasking: out = mask * x, mask from 64-iteration sharpened-softmax
// dropout recurrence on h = MLP(x).
//
// R2: incremental multiplicative softmax. Instead of recomputing
// logits/max/exp each iteration, maintain p = unnormalized softmax weight:
//   p <- p * (1 - yhat)^{1/T}   (exact up to an eps/(m+eps) term that is
//                                only nonzero when yhat is already ~0)
//   m <- m * (1 - yhat)
// Removes the per-iter max reduce, per-dim log and per-dim exp.

#define DD       640
#define HID      64
#define N_ITER   64
#define INV_T    (1.0f / 0.07f)
#define LOG2E    1.4426950408889634f
#define RPC      8            // rows per CTA
#define KPL      20           // elements per lane = 640/32

__device__ __forceinline__ float ex2f(float x) {
    float r; asm("ex2.approx.ftz.f32 %0, %1;" : "=f"(r) : "f"(x)); return r;
}
__device__ __forceinline__ float lg2f(float x) {
    float r; asm("lg2.approx.ftz.f32 %0, %1;" : "=f"(r) : "f"(x)); return r;
}

__global__ __launch_bounds__(RPC * 32)
void dim_masking_kernel(const float* __restrict__ x,
                        const float* __restrict__ W1,
                        const float* __restrict__ b1,
                        const float* __restrict__ W2,
                        const float* __restrict__ b2,
                        float* __restrict__ out)
{
    __shared__ float xs[RPC][DD];
    __shared__ float hs[RPC][HID];

    const int w    = threadIdx.x >> 5;
    const int lane = threadIdx.x & 31;
    const int row  = blockIdx.x * RPC + w;

    const float* xr = x + (size_t)row * DD;

    // ---- stage x row into smem (coalesced) ----
    #pragma unroll
    for (int k = 0; k < KPL; k++)
        xs[w][lane + 32 * k] = xr[lane + 32 * k];
    __syncwarp();

    // ---- GEMM1: h_hid = relu(x @ W1 + b1); lane computes units 2l, 2l+1 ----
    float2 acc1 = *(const float2*)&b1[2 * lane];
    #pragma unroll 8
    for (int d = 0; d < DD; d++) {
        float  xd = xs[w][d];
        float2 wv = *(const float2*)&W1[d * HID + 2 * lane];
        acc1.x = fmaf(xd, wv.x, acc1.x);
        acc1.y = fmaf(xd, wv.y, acc1.y);
    }
    hs[w][2 * lane]     = fmaxf(acc1.x, 0.0f);
    hs[w][2 * lane + 1] = fmaxf(acc1.y, 0.0f);
    __syncwarp();

    // ---- GEMM2: h = h_hid @ W2 + b2; lane owns dims j = lane + 32k ----
    float nh[KPL];   // -h
    #pragma unroll
    for (int k = 0; k < KPL; k++)
        nh[k] = b2[lane + 32 * k];
    #pragma unroll 4
    for (int c = 0; c < HID; c++) {
        float hc = hs[w][c];
        const float* w2r = &W2[c * DD + lane];
        #pragma unroll
        for (int k = 0; k < KPL; k++)
            nh[k] = fmaf(hc, w2r[32 * k], nh[k]);
    }

    // ---- init: p = exp2(lp - max lp), lp = -h/T in log2; m = 1 ----
    float p[KPL], m[KPL];
    float M0 = -3.402823e38f;
    #pragma unroll
    for (int k = 0; k < KPL; k++) {
        nh[k] = -nh[k] * (INV_T * LOG2E);   // now log2-domain logits
        M0 = fmaxf(M0, nh[k]);
    }
    #pragma unroll
    for (int o = 16; o > 0; o >>= 1)
        M0 = fmaxf(M0, __shfl_xor_sync(0xffffffffu, M0, o));
    #pragma unroll
    for (int k = 0; k < KPL; k++) {
        p[k] = ex2f(nh[k] - M0);
        m[k] = 1.0f;
    }

    // ---- 64-iteration incremental recurrence ----
    #pragma unroll 1
    for (int it = 0; it < N_ITER; it++) {
        float S0 = 0.0f, S1 = 0.0f;
        #pragma unroll
        for (int k = 0; k < KPL; k += 2) {
            S0 += p[k];
            S1 += p[k + 1];
        }
        float S = S0 + S1;
        #pragma unroll
        for (int o = 16; o > 0; o >>= 1)
            S += __shfl_xor_sync(0xffffffffu, S, o);
        float rS = __fdividef(1.0f, S);

        #pragma unroll
        for (int k = 0; k < KPL; k++) {
            float y = fminf(p[k] * rS, 1.0f);         // yhat
            float a = 1.0f - y;                        // ratio (m'+eps)/(m+eps)
            float f = ex2f(lg2f(a) * INV_T);           // ratio^{1/T}; a=0 -> 0
            p[k] *= f;
            m[k] = fmaf(-y, m[k], m[k]);               // m *= (1 - y)
        }
    }

    // ---- out = m * x ----
    float* orow = out + (size_t)row * DD;
    #pragma unroll
    for (int k = 0; k < KPL; k++)
        orow[lane + 32 * k] = m[k] * xs[w][lane + 32 * k];
}

extern "C" void kernel_launch(void* const* d_in, const int* in_sizes, int n_in,
                              void* d_out, int out_size)
{
    const float* x  = (const float*)d_in[0];   // (8192, 640)
    const float* W1 = (const float*)d_in[1];   // (640, 64)
    const float* b1 = (const float*)d_in[2];   // (64,)
    const float* W2 = (const float*)d_in[3];   // (64, 640)
    const float* b2 = (const float*)d_in[4];   // (640,)
    float* out = (float*)d_out;

    const int B = in_sizes[0] / DD;            // 8192
    dim_masking_kernel<<<B / RPC, RPC * 32>>>(x, W1, b1, W2, b2, out);
}

// round 4
// speedup vs baseline: 1.5201x; 1.0803x over previous
#include <cuda_runtime.h>
#include <cuda_bf16.h>

// DimMasking R3: incremental multiplicative softmax with
//  (a) degree-4 polynomial for (1-y)^{1/T} when y <= 0.02 (rare exact fallback)
//  (b) packed f32x2 math (FFMA2) throughout the scan and GEMM2
// Lane owns contiguous dim pairs d = 2*lane + 64*j, j=0..9.

#define DD       640
#define HID      64
#define N_ITER   64
#define INV_T    (1.0f / 0.07f)
#define LOG2E    1.4426950408889634f
#define RPC      8
#define NP       10          // pairs per lane (640 / 32 / 2)
#define YT       0.02f

// Taylor coeffs of (1-y)^a, a = 1/0.07, in z=-y: 1+z(C1+z(C2+z(C3+z*C4)))
#define C1F 14.285714285714286f
#define C2F 94.89795918367347f
#define C3F 388.6297376093295f
#define C4F 1096.4906ف

// (typo-proof numeric below in code)

typedef unsigned long long u64;

__device__ __forceinline__ u64 fma2(u64 a, u64 b, u64 c) {
    u64 d; asm("fma.rn.f32x2 %0, %1, %2, %3;" : "=l"(d) : "l"(a), "l"(b), "l"(c)); return d;
}
__device__ __forceinline__ u64 mul2(u64 a, u64 b) {
    u64 d; asm("mul.rn.f32x2 %0, %1, %2;" : "=l"(d) : "l"(a), "l"(b)); return d;
}
__device__ __forceinline__ u64 add2(u64 a, u64 b) {
    u64 d; asm("add.rn.f32x2 %0, %1, %2;" : "=l"(d) : "l"(a), "l"(b)); return d;
}
__device__ __forceinline__ u64 pack2(float x, float y) {
    u64 r; asm("mov.b64 %0, {%1, %2};" : "=l"(r) : "f"(x), "f"(y)); return r;
}
__device__ __forceinline__ float2 unpack2(u64 v) {
    float2 f; asm("mov.b64 {%0, %1}, %2;" : "=f"(f.x), "=f"(f.y) : "l"(v)); return f;
}
__device__ __forceinline__ float ex2f(float x) {
    float r; asm("ex2.approx.ftz.f32 %0, %1;" : "=f"(r) : "f"(x)); return r;
}
__device__ __forceinline__ float lg2f(float x) {
    float r; asm("lg2.approx.ftz.f32 %0, %1;" : "=f"(r) : "f"(x)); return r;
}
__device__ __forceinline__ float rcpf(float x) {
    float r; asm("rcp.approx.ftz.f32 %0, %1;" : "=f"(r) : "f"(x)); return r;
}

__global__ __launch_bounds__(RPC * 32)
void dim_masking_kernel(const float* __restrict__ x,
                        const float* __restrict__ W1,
                        const float* __restrict__ b1,
                        const float* __restrict__ W2,
                        const float* __restrict__ b2,
                        float* __restrict__ out)
{
    __shared__ float2 xs2[RPC][DD / 2];
    __shared__ float2 hs2[RPC][HID / 2];

    const int w    = threadIdx.x >> 5;
    const int lane = threadIdx.x & 31;
    const int row  = blockIdx.x * RPC + w;

    const u64* xr = (const u64*)(x + (size_t)row * DD);

    // ---- stage x row into smem as pairs (coalesced LDG.64/STS.64) ----
    #pragma unroll
    for (int j = 0; j < NP; j++)
        *(u64*)&xs2[w][lane + 32 * j] = xr[lane + 32 * j];
    __syncwarp();

    const float* xsf = (const float*)xs2[w];

    // ---- GEMM1: hidden units (2*lane, 2*lane+1) via packed FMA ----
    u64 acc1 = *(const u64*)&b1[2 * lane];
    #pragma unroll 8
    for (int d = 0; d < DD; d++) {
        float xd = xsf[d];
        u64 xv = pack2(xd, xd);
        u64 wv = *(const u64*)&W1[d * HID + 2 * lane];
        acc1 = fma2(xv, wv, acc1);
    }
    {
        float2 a = unpack2(acc1);
        hs2[w][lane] = make_float2(fmaxf(a.x, 0.0f), fmaxf(a.y, 0.0f));
    }
    __syncwarp();

    const float* hsf = (const float*)hs2[w];

    // ---- GEMM2: h pairs at dims 2*lane + 64*j ----
    u64 h2[NP];
    #pragma unroll
    for (int j = 0; j < NP; j++)
        h2[j] = *(const u64*)&b2[2 * lane + 64 * j];
    #pragma unroll 4
    for (int c = 0; c < HID; c++) {
        float hc = hsf[c];
        u64 hv = pack2(hc, hc);
        const float* w2r = &W2[c * DD + 2 * lane];
        #pragma unroll
        for (int j = 0; j < NP; j++)
            h2[j] = fma2(hv, *(const u64*)&w2r[64 * j], h2[j]);
    }

    // ---- init: p = exp2(l - max l), l = -h * (1/T) * log2(e); m = 1 ----
    float lx[NP], ly[NP];
    float M0 = -3.402823e38f;
    #pragma unroll
    for (int j = 0; j < NP; j++) {
        float2 hf = unpack2(h2[j]);
        lx[j] = -hf.x * (INV_T * LOG2E);
        ly[j] = -hf.y * (INV_T * LOG2E);
        M0 = fmaxf(M0, fmaxf(lx[j], ly[j]));
    }
    #pragma unroll
    for (int o = 16; o > 0; o >>= 1)
        M0 = fmaxf(M0, __shfl_xor_sync(0xffffffffu, M0, o));

    u64 p[NP], m[NP];
    const u64 ONE2 = pack2(1.0f, 1.0f);
    #pragma unroll
    for (int j = 0; j < NP; j++) {
        p[j] = pack2(ex2f(lx[j] - M0), ex2f(ly[j] - M0));
        m[j] = ONE2;
    }

    const u64 K1 = pack2(14.285714285714286f, 14.285714285714286f);
    const u64 K2 = pack2(94.89795918367347f,  94.89795918367347f);
    const u64 K3 = pack2(388.6297376093295f,  388.6297376093295f);
    const u64 K4 = pack2(1096.491194f,        1096.491194f);

    // ---- 64-iteration incremental recurrence ----
    #pragma unroll 1
    for (int it = 0; it < N_ITER; it++) {
        // S = sum p (packed tree + warp reduce)
        u64 sa = add2(p[0], p[1]);
        u64 sb = add2(p[2], p[3]);
        u64 sc = add2(p[4], p[5]);
        u64 sd = add2(p[6], p[7]);
        sa = add2(sa, add2(p[8], p[9]));
        sb = add2(sb, sc);
        sa = add2(sa, add2(sb, sd));
        float2 sf = unpack2(sa);
        float S = sf.x + sf.y;
        #pragma unroll
        for (int o = 16; o > 0; o >>= 1)
            S += __shfl_xor_sync(0xffffffffu, S, o);
        float nrS = -rcpf(S);
        u64 nrS2 = pack2(nrS, nrS);

        #pragma unroll
        for (int j = 0; j < NP; j++) {
            u64 z = mul2(p[j], nrS2);           // z = -y = -p/S
            u64 t = fma2(z, K4, K3);
            t = fma2(z, t, K2);
            t = fma2(z, t, K1);
            u64 f = fma2(z, t, ONE2);           // (1+z)^{1/T}, |z|<=YT
            float2 zf = unpack2(z);
            if (fminf(zf.x, zf.y) < -YT) {      // rare exact path
                float2 ff = unpack2(f);
                if (zf.x < -YT)
                    ff.x = ex2f(lg2f(fmaxf(1.0f + zf.x, 0.0f)) * INV_T);
                if (zf.y < -YT)
                    ff.y = ex2f(lg2f(fmaxf(1.0f + zf.y, 0.0f)) * INV_T);
                f = pack2(ff.x, ff.y);
            }
            p[j] = mul2(p[j], f);
            m[j] = fma2(z, m[j], m[j]);          // m *= (1 - y)
        }
    }

    // ---- out = m * x ----
    u64* orow = (u64*)(out + (size_t)row * DD);
    #pragma unroll
    for (int j = 0; j < NP; j++) {
        u64 xv = *(const u64*)&xs2[w][lane + 32 * j];
        orow[lane + 32 * j] = mul2(m[j], xv);
    }
}

extern "C" void kernel_launch(void* const* d_in, const int* in_sizes, int n_in,
                              void* d_out, int out_size)
{
    const float* x  = (const float*)d_in[0];   // (8192, 640)
    const float* W1 = (const float*)d_in[1];   // (640, 64)
    const float* b1 = (const float*)d_in[2];   // (64,)
    const float* W2 = (const float*)d_in[3];   // (64, 640)
    const float* b2 = (const float*)d_in[4];   // (640,)
    float* out = (float*)d_out;

    const int B = in_sizes[0] / DD;            // 8192
    dim_masking_kernel<<<B / RPC, RPC * 32>>>(x, W1, b1, W2, b2, out);
}